// round 15
// baseline (speedup 1.0000x reference)
#include <cuda_runtime.h>
#include <cstdint>

#define TT 512
#define IDIM 512
#define H 1024
#define G 4096
#define NB 128
#define NT_ENC 256
#define NT_DEC 288
#define FPAD 32    // one 128B line per counter
#define NGRP 32    // 4 blocks/counter -> 32 releases/step/counter

// ---------------- device scratch ----------------
__device__ __align__(16) float d_pre[(size_t)G * TT];       // W_ih_e@x_t + biases   [r][t]
__device__ __align__(16) float d_EH[(size_t)(TT + 1) * H];  // eh rows; row0 = 0
__device__ __align__(16) float d_DH[(size_t)(TT + 1) * H];  // dh rows; row0 = 0
__device__ unsigned d_fe[NGRP * FPAD], d_fd[NGRP * FPAD];   // padded group counters

__device__ __forceinline__ float sigf(float x) { return 1.f / (1.f + __expf(-x)); }
__device__ __forceinline__ float dot4(float4 a, float4 b) {
  return a.x * b.x + a.y * b.y + a.z * b.z + a.w * b.w;
}
__device__ __forceinline__ float wredsum(float v) {
#pragma unroll
  for (int o = 16; o; o >>= 1) v += __shfl_xor_sync(0xffffffffu, v, o);
  return v;
}
__device__ __forceinline__ float wredmax(float v) {
#pragma unroll
  for (int o = 16; o; o >>= 1) v = fmaxf(v, __shfl_xor_sync(0xffffffffu, v, o));
  return v;
}
__device__ __forceinline__ unsigned ld_acq(const unsigned* p) {
  unsigned v;
  asm volatile("ld.acquire.gpu.global.u32 %0, [%1];" : "=r"(v) : "l"(p) : "memory");
  return v;
}
__device__ __forceinline__ void red_rel(unsigned* p) {
  unsigned one = 1u;
  asm volatile("red.release.gpu.global.add.u32 [%0], %1;" :: "l"(p), "r"(one) : "memory");
}
// one warp: each lane acquire-loads ONE group counter; HOT SPIN (no nanosleep)
__device__ __forceinline__ void poll_groups(const unsigned* flags, int lane, unsigned tgt) {
  const unsigned* p = flags + (size_t)lane * FPAD;
  for (;;) {
    unsigned v = ld_acq(p);
    if (__all_sync(0xffffffffu, v >= tgt)) break;
  }
}

// gate combine: lanes 0-3 hold v = nonlin(gate_l); lane 0 updates cell, returns h (lane0)
__device__ __forceinline__ float lstm_combine(float v, float* cell) {
  float vi = __shfl_sync(0xffffffffu, v, 0);
  float vf = __shfl_sync(0xffffffffu, v, 1);
  float vg = __shfl_sync(0xffffffffu, v, 2);
  float vo = __shfl_sync(0xffffffffu, v, 3);
  float c = vf * (*cell) + vi * vg;
  *cell = c;
  return vo * tanhf(c);
}

// ---------------- init ----------------
__global__ void init_state() {
  int i = blockIdx.x * blockDim.x + threadIdx.x;
  if (i < H) { d_EH[i] = 0.f; d_DH[i] = 0.f; }
  if (i < NGRP * FPAD) { d_fe[i] = 0u; d_fd[i] = 0u; }
}

// ---------------- proven tiled GEMM: d_pre[r][t] = W_ih_e[r,:]·x_t + biases ----------------
#define BM 64
#define BN 64
#define BK 32
__global__ void __launch_bounds__(256) gemm_rowdot(const float* __restrict__ A, int lda,
                                                   const float* __restrict__ B, int ldb,
                                                   float* __restrict__ C, int K,
                                                   const float* __restrict__ bias0,
                                                   const float* __restrict__ bias1,
                                                   int hasBias) {
  __shared__ float As[BK][BM + 1];
  __shared__ float Bs[BK][BN + 1];
  int tid = threadIdx.x;
  int r0 = blockIdx.y * BM;
  int t0 = blockIdx.x * BN;
  int tx = tid & 15, ty = tid >> 4;
  float acc[4][4] = {};
  for (int k0 = 0; k0 < K; k0 += BK) {
#pragma unroll
    for (int i = 0; i < 8; ++i) {
      int lin = tid + i * 256;
      int m = lin >> 5, kk = lin & 31;
      As[kk][m] = A[(size_t)(r0 + m) * lda + k0 + kk];
      Bs[kk][m] = B[(size_t)(t0 + m) * ldb + k0 + kk];
    }
    __syncthreads();
#pragma unroll
    for (int kk = 0; kk < BK; ++kk) {
      float a[4], bv[4];
#pragma unroll
      for (int j = 0; j < 4; ++j) { a[j] = As[kk][ty * 4 + j]; bv[j] = Bs[kk][tx * 4 + j]; }
#pragma unroll
      for (int i2 = 0; i2 < 4; ++i2)
#pragma unroll
        for (int j = 0; j < 4; ++j) acc[i2][j] += a[i2] * bv[j];
    }
    __syncthreads();
  }
#pragma unroll
  for (int i2 = 0; i2 < 4; ++i2) {
    int r = r0 + ty * 4 + i2;
    float bias = hasBias ? (bias0[r] + bias1[r]) : 0.f;
#pragma unroll
    for (int j = 0; j < 4; ++j)
      C[(size_t)r * TT + (t0 + tx * 4 + j)] = acc[i2][j] + bias;
  }
}

// ---------------- encoder persistent ----------------
__global__ void __launch_bounds__(NT_ENC, 1)
enc_persist(const float* __restrict__ Whh_e) {
  __shared__ __align__(16) float shEh[H];
  const int b = blockIdx.x, tid = threadIdx.x;
  const int w = tid >> 5, lane = tid & 31;
  const int u = b * 8 + w;
  unsigned* myflag = &d_fe[(b >> 2) * FPAD];

  float4 wreg[4][8];
#pragma unroll
  for (int g = 0; g < 4; ++g) {
    const float4* p = (const float4*)(Whh_e + (size_t)(u + g * H) * H);
#pragma unroll
    for (int c = 0; c < 8; ++c) wreg[g][c] = __ldg(p + c * 32 + lane);
  }

  float ec = 0.f;
  for (int t = 0; t < TT; ++t) {
    // lanes 0-3 each prefetch their OWN gate's pre value
    float pre_l = 0.f;
    if (lane < 4) pre_l = __ldg(&d_pre[(size_t)(u + lane * H) * TT + t]);
    if (w == 0) poll_groups(d_fe, lane, 32u * (unsigned)t);
    __syncthreads();   // S1: prior-step stores visible
    ((float4*)shEh)[tid] = __ldcg((const float4*)(d_EH + (size_t)t * H) + tid);
    __syncthreads();   // S2: staged

    float a[4] = {0.f, 0.f, 0.f, 0.f};
#pragma unroll
    for (int c = 0; c < 8; ++c) {
      float4 hv = ((const float4*)shEh)[c * 32 + lane];
#pragma unroll
      for (int g = 0; g < 4; ++g) a[g] += dot4(wreg[g][c], hv);
    }
#pragma unroll
    for (int g = 0; g < 4; ++g) a[g] = wredsum(a[g]);   // all lanes hold all sums

    // parallel nonlinearity: lane l<4 computes its gate (2=tanh, else sigmoid)
    float gl = (lane < 4) ? (a[lane] + pre_l) : 0.f;
    float v = (lane == 2) ? tanhf(gl) : sigf(gl);
    float h = lstm_combine(v, &ec);
    if (lane == 0) {
      __stcg(&d_EH[(size_t)(t + 1) * H + u], h);
      red_rel(myflag);
    }
  }
}

// ---------------- decoder persistent: W_A·eh pre-poll; W_comb in regs ----------------
// smem: shWA [32][1024] 128KB | shDh 4KB | shS
#define SMEM_DEC_FLOATS (32 * 1024 + 1024 + 16)

__global__ void __launch_bounds__(NT_DEC, 1)
dec_persist(const float* __restrict__ Wihd, const float* __restrict__ Whhd,
            const float* __restrict__ bihd, const float* __restrict__ bhhd,
            const float* __restrict__ Wattn, const float* __restrict__ battn) {
  extern __shared__ __align__(16) float sh[];
  float* shWA = sh;                  // 32768 floats (W_A rows)
  float* shDh = sh + 32 * 1024;      // 1024
  float* shS  = shDh + 1024;         // 16

  const int b = blockIdx.x, tid = threadIdx.x;
  const int w = tid >> 5, lane = tid & 31;
  const int u = b * 8 + w;           // valid for w<8
  unsigned* myflag = &d_fd[(b >> 2) * FPAD];

  // W_A block rows -> smem: row jj = g*8+wv holds Wihd[(b*8+wv)+g*H][0:H]
  for (int i = tid; i < 32 * 256; i += NT_DEC) {
    int jj = i >> 8, c4 = i & 255;
    int g = jj >> 3, wv = jj & 7;
    ((float4*)shWA)[i] =
        __ldg((const float4*)(Wihd + ((size_t)(b * 8 + wv) + (size_t)g * H) * (2 * H)) + c4);
  }

  float4 wreg[4][8];                 // W_comb = W_ih_d[:,H:] + W_hh_d rows (dh coeffs)
  float bd[4] = {0.f, 0.f, 0.f, 0.f};
  if (w < 8) {
#pragma unroll
    for (int g = 0; g < 4; ++g) {
      const int row = u + g * H;
      const float4* pA = (const float4*)(Wihd + (size_t)row * (2 * H) + H);
      const float4* pB = (const float4*)(Whhd + (size_t)row * H);
#pragma unroll
      for (int c = 0; c < 8; ++c) {
        float4 x = __ldg(pA + c * 32 + lane), y = __ldg(pB + c * 32 + lane);
        wreg[g][c] = make_float4(x.x + y.x, x.y + y.y, x.z + y.z, x.w + y.w);
      }
      bd[g] = __ldg(bihd + row) + __ldg(bhhd + row);
    }
  }
  float awreg[16];                   // warp 8: softmaxed attention weights
#pragma unroll
  for (int j = 0; j < 16; ++j) awreg[j] = 0.f;
  __syncthreads();

  float dc = 0.f;
  for (int t = 0; t < TT; ++t) {
    // ======== PRE-POLL: everything depending only on eh_{t+1} (static) ========
    float pa[4] = {0.f, 0.f, 0.f, 0.f};
    float eEH = 0.f, bat = 0.f;
    if (w < 8) {
      const float4* ehp = (const float4*)(d_EH + (size_t)(t + 1) * H);
#pragma unroll
      for (int c = 0; c < 8; ++c) {
        float4 ehc = __ldcg(ehp + c * 32 + lane);
#pragma unroll
        for (int g = 0; g < 4; ++g)
          pa[g] += dot4(((const float4*)shWA)[(g * 8 + w) * 256 + c * 32 + lane], ehc);
      }
#pragma unroll
      for (int g = 0; g < 4; ++g) pa[g] = wredsum(pa[g]);
    } else {
      const float4* wrE = (const float4*)(Wattn + (size_t)t * (2 * H));
      const float4* ehp = (const float4*)(d_EH + (size_t)(t + 1) * H);
#pragma unroll
      for (int c = 0; c < 8; ++c)
        eEH += dot4(__ldg(wrE + c * 32 + lane), __ldcg(ehp + c * 32 + lane));
      bat = __ldg(&battn[t]);
      poll_groups(d_fd, lane, 32u * (unsigned)t);
    }
    __syncthreads();   // S1: dh_t visible; safe to restage shDh

    if (tid < 256)
      ((float4*)shDh)[tid] = __ldcg((const float4*)(d_DH + (size_t)t * H) + tid);
    __syncthreads();   // S2: staged

    // ======== POST-RENDEZVOUS: only dh-dependent work ========
    float a[4] = {0.f, 0.f, 0.f, 0.f};
    if (w < 8) {
#pragma unroll
      for (int c = 0; c < 8; ++c) {
        float4 dhc = ((const float4*)shDh)[c * 32 + lane];
#pragma unroll
        for (int g = 0; g < 4; ++g) a[g] += dot4(wreg[g][c], dhc);
      }
#pragma unroll
      for (int g = 0; g < 4; ++g) a[g] = wredsum(a[g]);
    } else {
      // dh-half of energy + register-resident softmax
      const float4* wrD = (const float4*)(Wattn + (size_t)t * (2 * H)) + 256;
      float e = eEH;
#pragma unroll
      for (int c = 0; c < 8; ++c) {
        int idx = c * 32 + lane;
        e += dot4(__ldg(wrD + idx), ((const float4*)shDh)[idx]);
      }
      e = wredsum(e) + bat;
      float vals[16];
      float m = -1e30f;
#pragma unroll
      for (int j = 0; j < 16; ++j) {
        float x = (j * 32 + lane == t) ? e : awreg[j];
        vals[j] = x;
        m = fmaxf(m, x);
      }
      m = wredmax(m);
      float ssum = 0.f;
#pragma unroll
      for (int j = 0; j < 16; ++j) { vals[j] = __expf(vals[j] - m); ssum += vals[j]; }
      ssum = wredsum(ssum);
      float inv = 1.f / ssum;
#pragma unroll
      for (int j = 0; j < 16; ++j) awreg[j] = vals[j] * inv;
      if (lane == 0) shS[0] = __expf(e - m) * inv;
    }
    __syncthreads();   // S3: shS published

    if (w < 8) {
      float s = shS[0];
      // parallel nonlinearity: lane l<4 owns gate l
      float gl = (lane < 4) ? (s * pa[lane] + a[lane] + bd[lane]) : 0.f;
      float v = (lane == 2) ? tanhf(gl) : sigf(gl);
      float h = lstm_combine(v, &dc);
      if (lane == 0) {
        __stcg(&d_DH[(size_t)(t + 1) * H + u], h);
        red_rel(myflag);
      }
    }
  }
}

// ---------------- out[t] = Wout @ dh_{t+1} + bout ----------------
__global__ void out_final(const float* __restrict__ Wout, const float* __restrict__ bout,
                          float* __restrict__ out) {
  const int w = threadIdx.x >> 5, lane = threadIdx.x & 31;
  const int t = blockIdx.x * 8 + w;
  const float4* wo = (const float4*)Wout;
  const float4* dh = (const float4*)(d_DH + (size_t)(t + 1) * H);
  float o = 0.f;
#pragma unroll
  for (int c = 0; c < 8; ++c) o += dot4(__ldg(wo + c * 32 + lane), __ldcg(dh + c * 32 + lane));
  o = wredsum(o);
  if (lane == 0) out[t] = o + __ldg(bout);
}

// ---------------- launch ----------------
extern "C" void kernel_launch(void* const* d_in, const int* in_sizes, int n_in,
                              void* d_out, int out_size) {
  const float* input_seq = (const float*)d_in[0];
  const float* W_ih_e = (const float*)d_in[2];
  const float* W_hh_e = (const float*)d_in[3];
  const float* b_ih_e = (const float*)d_in[4];
  const float* b_hh_e = (const float*)d_in[5];
  const float* W_attn = (const float*)d_in[6];
  const float* b_attn = (const float*)d_in[7];
  const float* W_ih_d = (const float*)d_in[8];
  const float* W_hh_d = (const float*)d_in[9];
  const float* b_ih_d = (const float*)d_in[10];
  const float* b_hh_d = (const float*)d_in[11];
  const float* W_out  = (const float*)d_in[12];
  const float* b_out  = (const float*)d_in[13];
  float* out = (float*)d_out;

  float* pre_ptr = nullptr;
  cudaGetSymbolAddress((void**)&pre_ptr, d_pre);   // device address, NOT host shadow

  const int smem_dec = SMEM_DEC_FLOATS * 4;        // ~135KB
  cudaFuncSetAttribute(dec_persist, cudaFuncAttributeMaxDynamicSharedMemorySize, smem_dec);

  init_state<<<8, 256>>>();
  gemm_rowdot<<<dim3(TT / BN, G / BM), 256>>>(W_ih_e, IDIM, input_seq, IDIM,
                                              pre_ptr, IDIM, b_ih_e, b_hh_e, 1);
  enc_persist<<<NB, NT_ENC>>>(W_hh_e);
  dec_persist<<<NB, NT_DEC, smem_dec>>>(W_ih_d, W_hh_d, b_ih_d, b_hh_d, W_attn, b_attn);
  out_final<<<TT / 8, 256>>>(W_out, b_out, out);
}

// round 16
// speedup vs baseline: 1.1800x; 1.1800x over previous
#include <cuda_runtime.h>
#include <cstdint>

#define TT 512
#define IDIM 512
#define H 1024
#define G 4096
#define NB 128
#define SENT 0x7FBFFFFFu   // NaN pattern; never produced by sig*tanh outputs

// ---------------- device scratch ----------------
__device__ __align__(16) float d_pre[(size_t)G * TT];       // W_ih_e@x_t + biases [r][t]
__device__ __align__(16) float d_EH[(size_t)(TT + 1) * H];  // eh rows; row0=0, rest sentinel
__device__ __align__(16) float d_DH[(size_t)(TT + 1) * H];  // dh rows; row0=0, rest sentinel

__device__ __forceinline__ float sigf(float x) { return 1.f / (1.f + __expf(-x)); }
__device__ __forceinline__ float dot4(float4 a, float4 b) {
  return a.x * b.x + a.y * b.y + a.z * b.z + a.w * b.w;
}
__device__ __forceinline__ float wredsum(float v) {
#pragma unroll
  for (int o = 16; o; o >>= 1) v += __shfl_xor_sync(0xffffffffu, v, o);
  return v;
}
__device__ __forceinline__ float wredmax(float v) {
#pragma unroll
  for (int o = 16; o; o >>= 1) v = fmaxf(v, __shfl_xor_sync(0xffffffffu, v, o));
  return v;
}
__device__ __forceinline__ uint4 ld_cg_u4(const uint4* p) {
  uint4 v;
  asm volatile("ld.global.cg.v4.u32 {%0,%1,%2,%3}, [%4];"
               : "=r"(v.x), "=r"(v.y), "=r"(v.z), "=r"(v.w) : "l"(p) : "memory");
  return v;
}
__device__ __forceinline__ uint4 poll_row4(const uint4* p) {
  uint4 v = ld_cg_u4(p);
  while (v.x == SENT || v.y == SENT || v.z == SENT || v.w == SENT) {
    __nanosleep(32);
    v = ld_cg_u4(p);
  }
  return v;
}
// lanes 0-3 hold nonlin(gate_l); all lanes get h; cell updated
__device__ __forceinline__ float lstm_combine(float v, float* cell) {
  float vi = __shfl_sync(0xffffffffu, v, 0);
  float vf = __shfl_sync(0xffffffffu, v, 1);
  float vg = __shfl_sync(0xffffffffu, v, 2);
  float vo = __shfl_sync(0xffffffffu, v, 3);
  float c = vf * (*cell) + vi * vg;
  *cell = c;
  return vo * tanhf(c);
}

// ---------------- init: row0 = 0, rows 1..TT = sentinel ----------------
__global__ void init_state() {
  const int n = (TT + 1) * H;
  for (int i = blockIdx.x * blockDim.x + threadIdx.x; i < n; i += gridDim.x * blockDim.x) {
    unsigned v = (i < H) ? 0u : SENT;
    ((unsigned*)d_EH)[i] = v;
    ((unsigned*)d_DH)[i] = v;
  }
}

// ---------------- proven tiled GEMM: d_pre[r][t] = W_ih_e[r,:]·x_t + biases ----------------
#define BM 64
#define BN 64
#define BK 32
__global__ void __launch_bounds__(256) gemm_rowdot(const float* __restrict__ A, int lda,
                                                   const float* __restrict__ B, int ldb,
                                                   float* __restrict__ C, int K,
                                                   const float* __restrict__ bias0,
                                                   const float* __restrict__ bias1,
                                                   int hasBias) {
  __shared__ float As[BK][BM + 1];
  __shared__ float Bs[BK][BN + 1];
  int tid = threadIdx.x;
  int r0 = blockIdx.y * BM;
  int t0 = blockIdx.x * BN;
  int tx = tid & 15, ty = tid >> 4;
  float acc[4][4] = {};
  for (int k0 = 0; k0 < K; k0 += BK) {
#pragma unroll
    for (int i = 0; i < 8; ++i) {
      int lin = tid + i * 256;
      int m = lin >> 5, kk = lin & 31;
      As[kk][m] = A[(size_t)(r0 + m) * lda + k0 + kk];
      Bs[kk][m] = B[(size_t)(t0 + m) * ldb + k0 + kk];
    }
    __syncthreads();
#pragma unroll
    for (int kk = 0; kk < BK; ++kk) {
      float a[4], bv[4];
#pragma unroll
      for (int j = 0; j < 4; ++j) { a[j] = As[kk][ty * 4 + j]; bv[j] = Bs[kk][tx * 4 + j]; }
#pragma unroll
      for (int i2 = 0; i2 < 4; ++i2)
#pragma unroll
        for (int j = 0; j < 4; ++j) acc[i2][j] += a[i2] * bv[j];
    }
    __syncthreads();
  }
#pragma unroll
  for (int i2 = 0; i2 < 4; ++i2) {
    int r = r0 + ty * 4 + i2;
    float bias = hasBias ? (bias0[r] + bias1[r]) : 0.f;
#pragma unroll
    for (int j = 0; j < 4; ++j)
      C[(size_t)r * TT + (t0 + tx * 4 + j)] = acc[i2][j] + bias;
  }
}

// ---------------- encoder: 16 warps, 2 warps per unit (K-split), sentinel sync ----------------
__global__ void __launch_bounds__(512, 1)
enc_persist(const float* __restrict__ Whh_e) {
  __shared__ __align__(16) float shEh[H];
  __shared__ float shPart[16][4];
  const int b = blockIdx.x, tid = threadIdx.x;
  const int w = tid >> 5, lane = tid & 31;
  const int half = w >> 3, wu = w & 7;
  const int u = b * 8 + wu;

  // half-row weights: 4 gates x 4 f4 per lane (64 regs)
  float4 wreg[4][4];
#pragma unroll
  for (int g = 0; g < 4; ++g) {
    const float4* p = (const float4*)(Whh_e + (size_t)(u + g * H) * H) + half * 128;
#pragma unroll
    for (int c = 0; c < 4; ++c) wreg[g][c] = __ldg(p + c * 32 + lane);
  }

  float ec = 0.f;
  for (int t = 0; t < TT; ++t) {
    float pre_l = 0.f;
    if (w < 8 && lane < 4) pre_l = __ldg(&d_pre[(size_t)(u + lane * H) * TT + t]);
    if (tid < 256) {
      uint4 hv = poll_row4((const uint4*)(d_EH + (size_t)t * H) + tid);
      ((uint4*)shEh)[tid] = hv;
    }
    __syncthreads();   // S1: staged

    float a[4] = {0.f, 0.f, 0.f, 0.f};
#pragma unroll
    for (int c = 0; c < 4; ++c) {
      float4 hv = ((const float4*)shEh)[half * 128 + c * 32 + lane];
#pragma unroll
      for (int g = 0; g < 4; ++g) a[g] += dot4(wreg[g][c], hv);
    }
#pragma unroll
    for (int g = 0; g < 4; ++g) a[g] = wredsum(a[g]);
    if (lane < 4) shPart[w][lane] = a[lane];
    __syncthreads();   // S2: partials visible

    if (w < 8) {
      float gl = (lane < 4) ? (shPart[w][lane] + shPart[w + 8][lane] + pre_l) : 0.f;
      float v = (lane == 2) ? tanhf(gl) : sigf(gl);
      float h = lstm_combine(v, &ec);
      if (lane == 0) __stcg(&d_EH[(size_t)(t + 1) * H + u], h);   // data IS the flag
    }
    __syncthreads();   // S3: shEh/shPart reads done before next-iter overwrite
  }
}

// ---------------- decoder: 17 warps, 2 warps/unit K-split, warp16 softmax ----------------
// dynamic smem floats: shWA 32768 | shEh 1024 | shDh 1024 | shPC 64 | shPA 64 | shS 16
#define SMEM_DEC_FLOATS (32 * 1024 + 1024 + 1024 + 64 + 64 + 16)

__global__ void __launch_bounds__(544, 1)
dec_persist(const float* __restrict__ Wihd, const float* __restrict__ Whhd,
            const float* __restrict__ bihd, const float* __restrict__ bhhd,
            const float* __restrict__ Wattn, const float* __restrict__ battn) {
  extern __shared__ __align__(16) float sh[];
  float* shWA = sh;                         // 32768
  float* shEh = sh + 32 * 1024;             // 1024
  float* shDh = shEh + 1024;                // 1024
  float (*shPC)[4] = (float(*)[4])(shDh + 1024);        // [16][4]
  float (*shPA)[4] = (float(*)[4])(shDh + 1024 + 64);   // [16][4]
  float* shS = shDh + 1024 + 128;           // 16

  const int b = blockIdx.x, tid = threadIdx.x;
  const int w = tid >> 5, lane = tid & 31;
  const int half = w >> 3, wu = w & 7;      // valid for w<16
  const int u = b * 8 + wu;

  // W_A rows -> smem (row jj = g*8+wv)
  for (int i = tid; i < 32 * 256; i += 544) {
    int jj = i >> 8, c4 = i & 255;
    int g = jj >> 3, wv = jj & 7;
    ((float4*)shWA)[i] =
        __ldg((const float4*)(Wihd + ((size_t)(b * 8 + wv) + (size_t)g * H) * (2 * H)) + c4);
  }

  // W_comb half-rows in regs (64 regs)
  float4 wregC[4][4];
  float bd_l = 0.f;
  if (w < 16) {
#pragma unroll
    for (int g = 0; g < 4; ++g) {
      const size_t row = (size_t)u + (size_t)g * H;
      const float4* pA = (const float4*)(Wihd + row * (2 * H) + H) + half * 128;
      const float4* pB = (const float4*)(Whhd + row * H) + half * 128;
#pragma unroll
      for (int c = 0; c < 4; ++c) {
        float4 x = __ldg(pA + c * 32 + lane), y = __ldg(pB + c * 32 + lane);
        wregC[g][c] = make_float4(x.x + y.x, x.y + y.y, x.z + y.z, x.w + y.w);
      }
    }
    if (w < 8 && lane < 4)
      bd_l = __ldg(bihd + u + lane * H) + __ldg(bhhd + u + lane * H);
  }
  float awreg[16];   // warp16 softmax state
#pragma unroll
  for (int j = 0; j < 16; ++j) awreg[j] = 0.f;
  __syncthreads();

  float dc = 0.f;
  for (int t = 0; t < TT; ++t) {
    // stage eh (static, no poll) + poll/stage dh; warp16 prefetches energy eh-half
    float eEH = 0.f, bat = 0.f;
    float4 wrD[8];
    if (tid < 256) {
      ((float4*)shEh)[tid] = __ldcg((const float4*)(d_EH + (size_t)(t + 1) * H) + tid);
      uint4 hv = poll_row4((const uint4*)(d_DH + (size_t)t * H) + tid);
      ((uint4*)shDh)[tid] = hv;
    } else if (w == 16) {
      const float4* wrE = (const float4*)(Wattn + (size_t)t * (2 * H));
      const float4* ehp = (const float4*)(d_EH + (size_t)(t + 1) * H);
#pragma unroll
      for (int c = 0; c < 8; ++c) {
        eEH += dot4(__ldg(wrE + c * 32 + lane), __ldcg(ehp + c * 32 + lane));
        wrD[c] = __ldg(wrE + 256 + c * 32 + lane);
      }
      bat = __ldg(&battn[t]);
    }
    __syncthreads();   // S1: staged

    if (w < 16) {
      float aC[4] = {0.f, 0.f, 0.f, 0.f};
      float aA[4] = {0.f, 0.f, 0.f, 0.f};
#pragma unroll
      for (int c = 0; c < 4; ++c) {
        int idx = half * 128 + c * 32 + lane;
        float4 dhc = ((const float4*)shDh)[idx];
        float4 ehc = ((const float4*)shEh)[idx];
#pragma unroll
        for (int g = 0; g < 4; ++g) {
          aC[g] += dot4(wregC[g][c], dhc);
          aA[g] += dot4(((const float4*)shWA)[(g * 8 + wu) * 256 + idx], ehc);
        }
      }
#pragma unroll
      for (int g = 0; g < 4; ++g) { aC[g] = wredsum(aC[g]); aA[g] = wredsum(aA[g]); }
      if (lane < 4) { shPC[w][lane] = aC[lane]; shPA[w][lane] = aA[lane]; }
    } else {
      // dh-half of energy + register softmax
      float e = eEH;
#pragma unroll
      for (int c = 0; c < 8; ++c)
        e += dot4(wrD[c], ((const float4*)shDh)[c * 32 + lane]);
      e = wredsum(e) + bat;
      float vals[16];
      float m = -1e30f;
#pragma unroll
      for (int j = 0; j < 16; ++j) {
        float x = (j * 32 + lane == t) ? e : awreg[j];
        vals[j] = x;
        m = fmaxf(m, x);
      }
      m = wredmax(m);
      float ssum = 0.f;
#pragma unroll
      for (int j = 0; j < 16; ++j) { vals[j] = __expf(vals[j] - m); ssum += vals[j]; }
      ssum = wredsum(ssum);
      float inv = 1.f / ssum;
#pragma unroll
      for (int j = 0; j < 16; ++j) awreg[j] = vals[j] * inv;
      if (lane == 0) shS[0] = __expf(e - m) * inv;
    }
    __syncthreads();   // S2: partials + shS visible

    if (w < 8) {
      float s = shS[0];
      float gl = (lane < 4)
          ? (s * (shPA[w][lane] + shPA[w + 8][lane]) +
             shPC[w][lane] + shPC[w + 8][lane] + bd_l)
          : 0.f;
      float v = (lane == 2) ? tanhf(gl) : sigf(gl);
      float h = lstm_combine(v, &dc);
      if (lane == 0) __stcg(&d_DH[(size_t)(t + 1) * H + u], h);   // data IS the flag
    }
    __syncthreads();   // S3: smem reads done before next-iter overwrite
  }
}

// ---------------- out[t] = Wout @ dh_{t+1} + bout ----------------
__global__ void out_final(const float* __restrict__ Wout, const float* __restrict__ bout,
                          float* __restrict__ out) {
  const int w = threadIdx.x >> 5, lane = threadIdx.x & 31;
  const int t = blockIdx.x * 8 + w;
  const float4* wo = (const float4*)Wout;
  const float4* dh = (const float4*)(d_DH + (size_t)(t + 1) * H);
  float o = 0.f;
#pragma unroll
  for (int c = 0; c < 8; ++c) o += dot4(__ldg(wo + c * 32 + lane), __ldcg(dh + c * 32 + lane));
  o = wredsum(o);
  if (lane == 0) out[t] = o + __ldg(bout);
}

// ---------------- launch ----------------
extern "C" void kernel_launch(void* const* d_in, const int* in_sizes, int n_in,
                              void* d_out, int out_size) {
  const float* input_seq = (const float*)d_in[0];
  const float* W_ih_e = (const float*)d_in[2];
  const float* W_hh_e = (const float*)d_in[3];
  const float* b_ih_e = (const float*)d_in[4];
  const float* b_hh_e = (const float*)d_in[5];
  const float* W_attn = (const float*)d_in[6];
  const float* b_attn = (const float*)d_in[7];
  const float* W_ih_d = (const float*)d_in[8];
  const float* W_hh_d = (const float*)d_in[9];
  const float* b_ih_d = (const float*)d_in[10];
  const float* b_hh_d = (const float*)d_in[11];
  const float* W_out  = (const float*)d_in[12];
  const float* b_out  = (const float*)d_in[13];
  float* out = (float*)d_out;

  float* pre_ptr = nullptr;
  cudaGetSymbolAddress((void**)&pre_ptr, d_pre);   // device address, NOT host shadow

  const int smem_dec = SMEM_DEC_FLOATS * 4;        // ~140KB
  cudaFuncSetAttribute(dec_persist, cudaFuncAttributeMaxDynamicSharedMemorySize, smem_dec);

  init_state<<<256, 256>>>();
  gemm_rowdot<<<dim3(TT / BN, G / BM), 256>>>(W_ih_e, IDIM, input_seq, IDIM,
                                              pre_ptr, IDIM, b_ih_e, b_hh_e, 1);
  enc_persist<<<NB, 512>>>(W_hh_e);
  dec_persist<<<NB, 544, smem_dec>>>(W_ih_d, W_hh_d, b_ih_d, b_hh_d, W_attn, b_attn);
  out_final<<<TT / 8, 256>>>(W_out, b_out, out);
}

// round 17
// speedup vs baseline: 1.2503x; 1.0596x over previous
#include <cuda_runtime.h>
#include <cstdint>

#define TT 512
#define IDIM 512
#define H 1024
#define G 4096
#define NB 128
#define SENT 0x7FBFFFFFu   // NaN pattern; never produced by finite matvec or sig*tanh

// ---------------- device scratch ----------------
__device__ __align__(16) float d_pre[(size_t)G * TT];       // W_ih_e@x_t + biases [r][t]
__device__ __align__(16) float d_EH[(size_t)(TT + 1) * H];  // eh rows; row0=0, rest sentinel
__device__ __align__(16) float d_DH[(size_t)(TT + 1) * H];  // dh rows; row0=0, rest sentinel

__device__ __forceinline__ float sigf(float x) { return 1.f / (1.f + __expf(-x)); }
__device__ __forceinline__ float dot4(float4 a, float4 b) {
  return a.x * b.x + a.y * b.y + a.z * b.z + a.w * b.w;
}
__device__ __forceinline__ float wredsum(float v) {
#pragma unroll
  for (int o = 16; o; o >>= 1) v += __shfl_xor_sync(0xffffffffu, v, o);
  return v;
}
__device__ __forceinline__ float wredmax(float v) {
#pragma unroll
  for (int o = 16; o; o >>= 1) v = fmaxf(v, __shfl_xor_sync(0xffffffffu, v, o));
  return v;
}
__device__ __forceinline__ uint4 ld_cg_u4(const uint4* p) {
  uint4 v;
  asm volatile("ld.global.cg.v4.u32 {%0,%1,%2,%3}, [%4];"
               : "=r"(v.x), "=r"(v.y), "=r"(v.z), "=r"(v.w) : "l"(p) : "memory");
  return v;
}
__device__ __forceinline__ unsigned ld_cg_u1(const unsigned* p) {
  unsigned v;
  asm volatile("ld.global.cg.u32 %0, [%1];" : "=r"(v) : "l"(p) : "memory");
  return v;
}
__device__ __forceinline__ uint4 poll_row4(const uint4* p) {
  uint4 v = ld_cg_u4(p);
  while (v.x == SENT || v.y == SENT || v.z == SENT || v.w == SENT) {
    __nanosleep(32);
    v = ld_cg_u4(p);
  }
  return v;
}
__device__ __forceinline__ float poll_scalar(const float* p) {
  unsigned v = ld_cg_u1((const unsigned*)p);
  while (v == SENT) {
    __nanosleep(64);
    v = ld_cg_u1((const unsigned*)p);
  }
  return __uint_as_float(v);
}
// lanes 0-3 hold nonlin(gate_l); all lanes get h; cell updated
__device__ __forceinline__ float lstm_combine(float v, float* cell) {
  float vi = __shfl_sync(0xffffffffu, v, 0);
  float vf = __shfl_sync(0xffffffffu, v, 1);
  float vg = __shfl_sync(0xffffffffu, v, 2);
  float vo = __shfl_sync(0xffffffffu, v, 3);
  float c = vf * (*cell) + vi * vg;
  *cell = c;
  return vo * tanhf(c);
}

// ---------------- init: h rows sentinel; d_pre ALL sentinel (gemm overwrites) ----------------
__global__ void init_state() {
  const int n = (TT + 1) * H;
  for (int i = blockIdx.x * blockDim.x + threadIdx.x; i < n; i += gridDim.x * blockDim.x) {
    unsigned v = (i < H) ? 0u : SENT;
    ((unsigned*)d_EH)[i] = v;
    ((unsigned*)d_DH)[i] = v;
  }
  const size_t np = (size_t)G * TT;
  for (size_t i = blockIdx.x * blockDim.x + threadIdx.x; i < np;
       i += (size_t)gridDim.x * blockDim.x)
    ((unsigned*)d_pre)[i] = SENT;
}

// ---------------- proven tiled GEMM: d_pre[r][t] = W_ih_e[r,:]·x_t + biases ----------------
#define BM 64
#define BN 64
#define BK 32
__global__ void __launch_bounds__(256) gemm_rowdot(const float* __restrict__ A, int lda,
                                                   const float* __restrict__ B, int ldb,
                                                   float* __restrict__ C, int K,
                                                   const float* __restrict__ bias0,
                                                   const float* __restrict__ bias1,
                                                   int hasBias) {
  __shared__ float As[BK][BM + 1];
  __shared__ float Bs[BK][BN + 1];
  int tid = threadIdx.x;
  int r0 = blockIdx.y * BM;
  int t0 = blockIdx.x * BN;
  int tx = tid & 15, ty = tid >> 4;
  float acc[4][4] = {};
  for (int k0 = 0; k0 < K; k0 += BK) {
#pragma unroll
    for (int i = 0; i < 8; ++i) {
      int lin = tid + i * 256;
      int m = lin >> 5, kk = lin & 31;
      As[kk][m] = A[(size_t)(r0 + m) * lda + k0 + kk];
      Bs[kk][m] = B[(size_t)(t0 + m) * ldb + k0 + kk];
    }
    __syncthreads();
#pragma unroll
    for (int kk = 0; kk < BK; ++kk) {
      float a[4], bv[4];
#pragma unroll
      for (int j = 0; j < 4; ++j) { a[j] = As[kk][ty * 4 + j]; bv[j] = Bs[kk][tx * 4 + j]; }
#pragma unroll
      for (int i2 = 0; i2 < 4; ++i2)
#pragma unroll
        for (int j = 0; j < 4; ++j) acc[i2][j] += a[i2] * bv[j];
    }
    __syncthreads();
  }
#pragma unroll
  for (int i2 = 0; i2 < 4; ++i2) {
    int r = r0 + ty * 4 + i2;
    float bias = hasBias ? (bias0[r] + bias1[r]) : 0.f;
#pragma unroll
    for (int j = 0; j < 4; ++j)
      C[(size_t)r * TT + (t0 + tx * 4 + j)] = acc[i2][j] + bias;
  }
}

// ---------------- encoder: 16 warps, 2 per unit (K-split), sentinel sync ----------------
__global__ void __launch_bounds__(512, 1)
enc_persist(const float* __restrict__ Whh_e) {
  __shared__ __align__(16) float shEh[H];
  __shared__ float shPart[16][4];
  const int b = blockIdx.x, tid = threadIdx.x;
  const int w = tid >> 5, lane = tid & 31;
  const int half = w >> 3, wu = w & 7;
  const int u = b * 8 + wu;

  float4 wreg[4][4];
#pragma unroll
  for (int g = 0; g < 4; ++g) {
    const float4* p = (const float4*)(Whh_e + (size_t)(u + g * H) * H) + half * 128;
#pragma unroll
    for (int c = 0; c < 4; ++c) wreg[g][c] = __ldg(p + c * 32 + lane);
  }

  float ec = 0.f;
  for (int t = 0; t < TT; ++t) {
    // lanes 0-3 of gate warps poll their pre scalar (gemm runs concurrently)
    float pre_l = 0.f;
    if (w < 8 && lane < 4) pre_l = poll_scalar(&d_pre[(size_t)(u + lane * H) * TT + t]);
    if (tid < 256) {
      uint4 hv = poll_row4((const uint4*)(d_EH + (size_t)t * H) + tid);
      ((uint4*)shEh)[tid] = hv;
    }
    __syncthreads();   // S1: staged

    float a[4] = {0.f, 0.f, 0.f, 0.f};
#pragma unroll
    for (int c = 0; c < 4; ++c) {
      float4 hv = ((const float4*)shEh)[half * 128 + c * 32 + lane];
#pragma unroll
      for (int g = 0; g < 4; ++g) a[g] += dot4(wreg[g][c], hv);
    }
#pragma unroll
    for (int g = 0; g < 4; ++g) a[g] = wredsum(a[g]);
    if (lane < 4) shPart[w][lane] = a[lane];
    __syncthreads();   // S2: partials visible

    if (w < 8) {
      float gl = (lane < 4) ? (shPart[w][lane] + shPart[w + 8][lane] + pre_l) : 0.f;
      float v = (lane == 2) ? tanhf(gl) : sigf(gl);
      float h = lstm_combine(v, &ec);
      if (lane == 0) __stcg(&d_EH[(size_t)(t + 1) * H + u], h);   // data IS the flag
    }
    __syncthreads();   // S3: smem reads done before next-iter overwrite
  }
}

// ---------------- decoder: 17 warps, 2 warps/unit K-split, warp16 softmax ----------------
#define SMEM_DEC_FLOATS (32 * 1024 + 1024 + 1024 + 64 + 64 + 16)

__global__ void __launch_bounds__(544, 1)
dec_persist(const float* __restrict__ Wihd, const float* __restrict__ Whhd,
            const float* __restrict__ bihd, const float* __restrict__ bhhd,
            const float* __restrict__ Wattn, const float* __restrict__ battn) {
  extern __shared__ __align__(16) float sh[];
  float* shWA = sh;                         // 32768
  float* shEh = sh + 32 * 1024;             // 1024
  float* shDh = shEh + 1024;                // 1024
  float (*shPC)[4] = (float(*)[4])(shDh + 1024);        // [16][4]
  float (*shPA)[4] = (float(*)[4])(shDh + 1024 + 64);   // [16][4]
  float* shS = shDh + 1024 + 128;           // 16

  const int b = blockIdx.x, tid = threadIdx.x;
  const int w = tid >> 5, lane = tid & 31;
  const int half = w >> 3, wu = w & 7;      // valid for w<16
  const int u = b * 8 + wu;

  for (int i = tid; i < 32 * 256; i += 544) {
    int jj = i >> 8, c4 = i & 255;
    int g = jj >> 3, wv = jj & 7;
    ((float4*)shWA)[i] =
        __ldg((const float4*)(Wihd + ((size_t)(b * 8 + wv) + (size_t)g * H) * (2 * H)) + c4);
  }

  float4 wregC[4][4];
  float bd_l = 0.f;
  if (w < 16) {
#pragma unroll
    for (int g = 0; g < 4; ++g) {
      const size_t row = (size_t)u + (size_t)g * H;
      const float4* pA = (const float4*)(Wihd + row * (2 * H) + H) + half * 128;
      const float4* pB = (const float4*)(Whhd + row * H) + half * 128;
#pragma unroll
      for (int c = 0; c < 4; ++c) {
        float4 x = __ldg(pA + c * 32 + lane), y = __ldg(pB + c * 32 + lane);
        wregC[g][c] = make_float4(x.x + y.x, x.y + y.y, x.z + y.z, x.w + y.w);
      }
    }
    if (w < 8 && lane < 4)
      bd_l = __ldg(bihd + u + lane * H) + __ldg(bhhd + u + lane * H);
  }
  float awreg[16];
#pragma unroll
  for (int j = 0; j < 16; ++j) awreg[j] = 0.f;
  __syncthreads();

  float dc = 0.f;
  for (int t = 0; t < TT; ++t) {
    float eEH = 0.f, bat = 0.f;
    float4 wrD[8];
    if (tid < 256) {
      ((float4*)shEh)[tid] = __ldcg((const float4*)(d_EH + (size_t)(t + 1) * H) + tid);
      uint4 hv = poll_row4((const uint4*)(d_DH + (size_t)t * H) + tid);
      ((uint4*)shDh)[tid] = hv;
    } else if (w == 16) {
      const float4* wrE = (const float4*)(Wattn + (size_t)t * (2 * H));
      const float4* ehp = (const float4*)(d_EH + (size_t)(t + 1) * H);
#pragma unroll
      for (int c = 0; c < 8; ++c) {
        eEH += dot4(__ldg(wrE + c * 32 + lane), __ldcg(ehp + c * 32 + lane));
        wrD[c] = __ldg(wrE + 256 + c * 32 + lane);
      }
      bat = __ldg(&battn[t]);
    }
    __syncthreads();   // S1: staged

    if (w < 16) {
      float aC[4] = {0.f, 0.f, 0.f, 0.f};
      float aA[4] = {0.f, 0.f, 0.f, 0.f};
#pragma unroll
      for (int c = 0; c < 4; ++c) {
        int idx = half * 128 + c * 32 + lane;
        float4 dhc = ((const float4*)shDh)[idx];
        float4 ehc = ((const float4*)shEh)[idx];
#pragma unroll
        for (int g = 0; g < 4; ++g) {
          aC[g] += dot4(wregC[g][c], dhc);
          aA[g] += dot4(((const float4*)shWA)[(g * 8 + wu) * 256 + idx], ehc);
        }
      }
#pragma unroll
      for (int g = 0; g < 4; ++g) { aC[g] = wredsum(aC[g]); aA[g] = wredsum(aA[g]); }
      if (lane < 4) { shPC[w][lane] = aC[lane]; shPA[w][lane] = aA[lane]; }
    } else {
      float e = eEH;
#pragma unroll
      for (int c = 0; c < 8; ++c)
        e += dot4(wrD[c], ((const float4*)shDh)[c * 32 + lane]);
      e = wredsum(e) + bat;
      float vals[16];
      float m = -1e30f;
#pragma unroll
      for (int j = 0; j < 16; ++j) {
        float x = (j * 32 + lane == t) ? e : awreg[j];
        vals[j] = x;
        m = fmaxf(m, x);
      }
      m = wredmax(m);
      float ssum = 0.f;
#pragma unroll
      for (int j = 0; j < 16; ++j) { vals[j] = __expf(vals[j] - m); ssum += vals[j]; }
      ssum = wredsum(ssum);
      float inv = 1.f / ssum;
#pragma unroll
      for (int j = 0; j < 16; ++j) awreg[j] = vals[j] * inv;
      if (lane == 0) shS[0] = __expf(e - m) * inv;
    }
    __syncthreads();   // S2: partials + shS visible

    if (w < 8) {
      float s = shS[0];
      float gl = (lane < 4)
          ? (s * (shPA[w][lane] + shPA[w + 8][lane]) +
             shPC[w][lane] + shPC[w + 8][lane] + bd_l)
          : 0.f;
      float v = (lane == 2) ? tanhf(gl) : sigf(gl);
      float h = lstm_combine(v, &dc);
      if (lane == 0) __stcg(&d_DH[(size_t)(t + 1) * H + u], h);   // data IS the flag
    }
    __syncthreads();   // S3: smem reads done before next-iter overwrite
  }
}

// ---------------- out[t] = Wout @ dh_{t+1} + bout ----------------
__global__ void out_final(const float* __restrict__ Wout, const float* __restrict__ bout,
                          float* __restrict__ out) {
  const int w = threadIdx.x >> 5, lane = threadIdx.x & 31;
  const int t = blockIdx.x * 8 + w;
  const float4* wo = (const float4*)Wout;
  const float4* dh = (const float4*)(d_DH + (size_t)(t + 1) * H);
  float o = 0.f;
#pragma unroll
  for (int c = 0; c < 8; ++c) o += dot4(__ldg(wo + c * 32 + lane), __ldcg(dh + c * 32 + lane));
  o = wredsum(o);
  if (lane == 0) out[t] = o + __ldg(bout);
}

// ---------------- launch: gemm forked onto a second stream, hidden under enc ----------------
extern "C" void kernel_launch(void* const* d_in, const int* in_sizes, int n_in,
                              void* d_out, int out_size) {
  const float* input_seq = (const float*)d_in[0];
  const float* W_ih_e = (const float*)d_in[2];
  const float* W_hh_e = (const float*)d_in[3];
  const float* b_ih_e = (const float*)d_in[4];
  const float* b_hh_e = (const float*)d_in[5];
  const float* W_attn = (const float*)d_in[6];
  const float* b_attn = (const float*)d_in[7];
  const float* W_ih_d = (const float*)d_in[8];
  const float* W_hh_d = (const float*)d_in[9];
  const float* b_ih_d = (const float*)d_in[10];
  const float* b_hh_d = (const float*)d_in[11];
  const float* W_out  = (const float*)d_in[12];
  const float* b_out  = (const float*)d_in[13];
  float* out = (float*)d_out;

  float* pre_ptr = nullptr;
  cudaGetSymbolAddress((void**)&pre_ptr, d_pre);   // device address, NOT host shadow

  static cudaStream_t s2 = nullptr;
  static cudaEvent_t ev1 = nullptr, ev2 = nullptr;
  if (!s2) {
    cudaStreamCreateWithFlags(&s2, cudaStreamNonBlocking);
    cudaEventCreateWithFlags(&ev1, cudaEventDisableTiming);
    cudaEventCreateWithFlags(&ev2, cudaEventDisableTiming);
  }

  const int smem_dec = SMEM_DEC_FLOATS * 4;        // ~140KB
  cudaFuncSetAttribute(dec_persist, cudaFuncAttributeMaxDynamicSharedMemorySize, smem_dec);

  init_state<<<256, 256>>>();                       // default stream

  // fork: gemm on s2, concurrent with enc (enc polls d_pre sentinels)
  cudaEventRecord(ev1, 0);
  cudaStreamWaitEvent(s2, ev1, 0);
  gemm_rowdot<<<dim3(TT / BN, G / BM), 256, 0, s2>>>(W_ih_e, IDIM, input_seq, IDIM,
                                                     pre_ptr, IDIM, b_ih_e, b_hh_e, 1);
  cudaEventRecord(ev2, s2);

  enc_persist<<<NB, 512>>>(W_hh_e);                 // default stream, overlaps gemm

  cudaStreamWaitEvent(0, ev2, 0);                   // join fork before dec
  dec_persist<<<NB, 544, smem_dec>>>(W_ih_d, W_hh_d, b_ih_d, b_hh_d, W_attn, b_attn);
  out_final<<<TT / 8, 256>>>(W_out, b_out, out);
}